// round 8
// baseline (speedup 1.0000x reference)
#include <cuda_runtime.h>
#include <math.h>
#include <stdint.h>

#define D_    1024
#define H_    16
#define HD_   64
#define S_    2048
#define B_    4
#define T_    (B_*S_)      // 8192 tokens
#define DFF_  4096
#define SIXD_ 6144

// ---------------- scratch (static device globals; no allocation) ----------------
__device__ float g_mod [B_*SIXD_];
__device__ float g_xn  [(size_t)T_*D_];
__device__ float g_qkv [(size_t)T_*3*D_];
__device__ float g_q   [(size_t)B_*H_*S_*HD_];
__device__ float g_k   [(size_t)B_*H_*S_*HD_];
__device__ float g_v   [(size_t)B_*H_*S_*HD_];
__device__ float g_attn[(size_t)T_*D_];
__device__ float g_x2  [(size_t)T_*D_];
__device__ float g_h   [(size_t)T_*DFF_];
// tf32-rounded weight copies
__device__ float g_wqkv[(size_t)D_*3*D_];     // 12 MB
__device__ float g_wout[(size_t)D_*D_];       // 4 MB
__device__ float g_w1  [(size_t)D_*DFF_];     // 16 MB
__device__ float g_w2  [(size_t)DFF_*D_];     // 16 MB

// ---------------- async copy / mma helpers ---------------------------------------
__device__ __forceinline__ void cp_async16(float* smem, const float* gmem)
{
    uint32_t sa = (uint32_t)__cvta_generic_to_shared(smem);
    asm volatile("cp.async.cg.shared.global [%0], [%1], 16;\n"
                 :: "r"(sa), "l"(gmem));
}
#define CP_COMMIT()  asm volatile("cp.async.commit_group;\n" ::: "memory")
#define CP_WAIT1()   asm volatile("cp.async.wait_group 1;\n" ::: "memory")
#define CP_WAITALL() asm volatile("cp.async.wait_all;\n" ::: "memory")

__device__ __forceinline__ uint32_t f2tf(float x)
{
    uint32_t r;
    asm("cvt.rna.tf32.f32 %0, %1;\n" : "=r"(r) : "f"(x));
    return r;
}
__device__ __forceinline__ float rtf(float x)   // round to tf32, keep as float
{
    return __uint_as_float(f2tf(x));
}

__device__ __forceinline__ void mma_tf32(float* c, const uint32_t* a,
                                         const uint32_t* b)
{
    asm volatile("mma.sync.aligned.m16n8k8.row.col.f32.tf32.tf32.f32 "
                 "{%0,%1,%2,%3}, {%4,%5,%6,%7}, {%8,%9}, {%0,%1,%2,%3};\n"
                 : "+f"(c[0]), "+f"(c[1]), "+f"(c[2]), "+f"(c[3])
                 : "r"(a[0]), "r"(a[1]), "r"(a[2]), "r"(a[3]),
                   "r"(b[0]), "r"(b[1]));
}

// ---------------- tf32 pre-rounding of weights ------------------------------------
__global__ void round_tf32_kernel(const float* __restrict__ in,
                                  float* __restrict__ out)
{
    int i = blockIdx.x * 256 + threadIdx.x;
    float4 v = ((const float4*)in)[i];
    v.x = rtf(v.x); v.y = rtf(v.y); v.z = rtf(v.z); v.w = rtf(v.w);
    ((float4*)out)[i] = v;
}

// ---------------- adaLN modulation ------------------------------------------------
__global__ void mod_kernel(const float* __restrict__ c,
                           const float* __restrict__ adaW,
                           const float* __restrict__ adab,
                           float* __restrict__ mod)
{
    int b = blockIdx.y;
    int j = blockIdx.x * 256 + threadIdx.x;
    __shared__ float cs[D_];
    for (int i = threadIdx.x; i < D_; i += 256) cs[i] = c[b*D_ + i];
    __syncthreads();
    float acc = adab[j];
#pragma unroll 4
    for (int k = 0; k < D_; k++)
        acc = fmaf(cs[k], adaW[(size_t)k*SIXD_ + j], acc);
    mod[b*SIXD_ + j] = acc;
}

// ---------------- LayerNorm + modulate (tf32-rounded output) ----------------------
__global__ void ln_mod_kernel(const float* __restrict__ x,
                              const float* __restrict__ w,
                              const float* __restrict__ mod,
                              float* __restrict__ out,
                              int sh_off, int sc_off)
{
    int t = blockIdx.x;
    int b = t / S_;
    int tid = threadIdx.x;
    float4 v = ((const float4*)(x + (size_t)t*D_))[tid];
    float s  = v.x + v.y + v.z + v.w;
    float sq = v.x*v.x + v.y*v.y + v.z*v.z + v.w*v.w;
#pragma unroll
    for (int o = 16; o > 0; o >>= 1) {
        s  += __shfl_xor_sync(0xffffffffu, s,  o);
        sq += __shfl_xor_sync(0xffffffffu, sq, o);
    }
    __shared__ float ss[8], ssq[8];
    int warp = tid >> 5, lane = tid & 31;
    if (lane == 0) { ss[warp] = s; ssq[warp] = sq; }
    __syncthreads();
    if (warp == 0) {
        s  = (lane < 8) ? ss[lane]  : 0.f;
        sq = (lane < 8) ? ssq[lane] : 0.f;
#pragma unroll
        for (int o = 4; o > 0; o >>= 1) {
            s  += __shfl_xor_sync(0xffffffffu, s,  o);
            sq += __shfl_xor_sync(0xffffffffu, sq, o);
        }
        if (lane == 0) { ss[0] = s; ssq[0] = sq; }
    }
    __syncthreads();
    s = ss[0]; sq = ssq[0];
    float mu   = s  * (1.f/D_);
    float var  = sq * (1.f/D_) - mu*mu;
    float rsig = rsqrtf(var + 1e-5f);

    const float* modb = mod + b*SIXD_;
    float4 wv  = ((const float4*)w)[tid];
    float4 shv = ((const float4*)(modb + sh_off))[tid];
    float4 scv = ((const float4*)(modb + sc_off))[tid];
    float4 r;
    r.x = rtf(fmaf((v.x-mu)*rsig*wv.x, (1.f+scv.x), shv.x));
    r.y = rtf(fmaf((v.y-mu)*rsig*wv.y, (1.f+scv.y), shv.y));
    r.z = rtf(fmaf((v.z-mu)*rsig*wv.z, (1.f+scv.z), shv.z));
    r.w = rtf(fmaf((v.w-mu)*rsig*wv.w, (1.f+scv.w), shv.w));
    ((float4*)(out + (size_t)t*D_))[tid] = r;
}

// ---------------- RMSNorm(q,k) + RoPE + relayout (tf32-rounded) -------------------
__global__ void qk_rope_kernel(const float* __restrict__ qkv,
                               const float* __restrict__ cosp,
                               const float* __restrict__ sinp,
                               const float* __restrict__ qw,
                               const float* __restrict__ kw,
                               float* __restrict__ Q,
                               float* __restrict__ K,
                               float* __restrict__ V)
{
    int t = blockIdx.x;
    int s = t % S_;
    int b = t / S_;
    int h    = threadIdx.x >> 5;
    int lane = threadIdx.x & 31;
    const float* base = qkv + (size_t)t*3*D_ + h*HD_;
    float q0 = base[lane],        q1 = base[lane+32];
    float k0 = base[D_+lane],     k1 = base[D_+lane+32];
    float v0 = base[2*D_+lane],   v1 = base[2*D_+lane+32];

    float qs = q0*q0 + q1*q1;
    float ks = k0*k0 + k1*k1;
#pragma unroll
    for (int o = 16; o > 0; o >>= 1) {
        qs += __shfl_xor_sync(0xffffffffu, qs, o);
        ks += __shfl_xor_sync(0xffffffffu, ks, o);
    }
    float qr = rsqrtf(qs*(1.f/HD_) + 1e-6f);
    float kr = rsqrtf(ks*(1.f/HD_) + 1e-6f);
    q0 *= qr*qw[lane];  q1 *= qr*qw[lane+32];
    k0 *= kr*kw[lane];  k1 *= kr*kw[lane+32];

    float c0 = cosp[s*HD_+lane], c1 = cosp[s*HD_+lane+32];
    float n0 = sinp[s*HD_+lane], n1 = sinp[s*HD_+lane+32];
    float qo0 = (q0*c0 - q1*n0) * 0.125f;
    float qo1 = (q1*c1 + q0*n1) * 0.125f;
    float ko0 =  k0*c0 - k1*n0;
    float ko1 =  k1*c1 + k0*n1;

    size_t o = ((size_t)(b*H_ + h)*S_ + s)*HD_;
    Q[o+lane] = rtf(qo0);  Q[o+lane+32] = rtf(qo1);
    K[o+lane] = rtf(ko0);  K[o+lane+32] = rtf(ko1);
    V[o+lane] = rtf(v0);   V[o+lane+32] = rtf(v1);
}

// ================= TF32 tensor-core flash attention (no mainloop cvt) =============
#define AQT 128
#define AKT 64
#define AQP 68
#define AKP 68
#define AVP 72
#define APP 68
#define ATTN_SMEM ((AQT*AQP + AKT*AKP + AKT*AVP + AQT*APP) * 4)   // 105472 B

__global__ __launch_bounds__(256, 2)
void attn_mma_kernel(const float* __restrict__ Q,
                     const float* __restrict__ K,
                     const float* __restrict__ V,
                     float* __restrict__ out)
{
    extern __shared__ float sm[];
    float* Qs = sm;
    float* Ks = Qs + AQT*AQP;
    float* Vs = Ks + AKT*AKP;
    float* Ps = Vs + AKT*AVP;

    int bh  = blockIdx.y;
    int qt  = blockIdx.x;
    int tid = threadIdx.x;
    int warp = tid >> 5, lane = tid & 31;
    int gid = lane >> 2, tig = lane & 3;
    int wm = warp * 16;

    const float* Qb = Q + ((size_t)bh*S_ + qt*AQT)*HD_;
    for (int it = tid; it < AQT*16; it += 256) {
        int r = it >> 4, c4 = (it & 15) * 4;
        cp_async16(&Qs[r*AQP + c4], Qb + r*HD_ + c4);
    }
    CP_COMMIT();

    float m0 = -1e30f, m1 = -1e30f, l0 = 0.f, l1 = 0.f;
    float oacc[8][4];
#pragma unroll
    for (int j = 0; j < 8; j++)
#pragma unroll
        for (int q = 0; q < 4; q++) oacc[j][q] = 0.f;

    const float* Kb0 = K + (size_t)bh*S_*HD_;
    const float* Vb0 = V + (size_t)bh*S_*HD_;

    for (int kt = 0; kt < S_/AKT; kt++) {
        const float* Kb = Kb0 + (size_t)kt*AKT*HD_;
        const float* Vb = Vb0 + (size_t)kt*AKT*HD_;
        for (int it = tid; it < AKT*16; it += 256) {
            int r = it >> 4, c4 = (it & 15) * 4;
            cp_async16(&Ks[r*AKP + c4], Kb + r*HD_ + c4);
            cp_async16(&Vs[r*AVP + c4], Vb + r*HD_ + c4);
        }
        CP_COMMIT();
        CP_WAITALL();
        __syncthreads();

        // ---- S = Q @ K^T (operands pre-rounded; raw bit loads) -----------------
        float sacc[8][4];
#pragma unroll
        for (int j = 0; j < 8; j++)
#pragma unroll
            for (int q = 0; q < 4; q++) sacc[j][q] = 0.f;

#pragma unroll
        for (int kc = 0; kc < 8; kc++) {
            uint32_t af[4];
            const float* qp = Qs + (wm + gid)*AQP + kc*8 + tig;
            af[0] = __float_as_uint(qp[0]);
            af[1] = __float_as_uint(qp[8*AQP]);
            af[2] = __float_as_uint(qp[4]);
            af[3] = __float_as_uint(qp[8*AQP + 4]);
#pragma unroll
            for (int j = 0; j < 8; j++) {
                uint32_t bf[2];
                const float* kp = Ks + (j*8 + gid)*AKP + kc*8 + tig;
                bf[0] = __float_as_uint(kp[0]);
                bf[1] = __float_as_uint(kp[4]);
                mma_tf32(sacc[j], af, bf);
            }
        }

        // ---- online softmax; round P to tf32 here (consistent with PV) ---------
        float mx0 = -1e30f, mx1 = -1e30f;
#pragma unroll
        for (int j = 0; j < 8; j++) {
            mx0 = fmaxf(mx0, fmaxf(sacc[j][0], sacc[j][1]));
            mx1 = fmaxf(mx1, fmaxf(sacc[j][2], sacc[j][3]));
        }
        mx0 = fmaxf(mx0, __shfl_xor_sync(0xffffffffu, mx0, 1));
        mx0 = fmaxf(mx0, __shfl_xor_sync(0xffffffffu, mx0, 2));
        mx1 = fmaxf(mx1, __shfl_xor_sync(0xffffffffu, mx1, 1));
        mx1 = fmaxf(mx1, __shfl_xor_sync(0xffffffffu, mx1, 2));
        float mn0 = fmaxf(m0, mx0), mn1 = fmaxf(m1, mx1);
        float al0 = __expf(m0 - mn0), al1 = __expf(m1 - mn1);
        float rs0 = 0.f, rs1 = 0.f;
#pragma unroll
        for (int j = 0; j < 8; j++) {
            float p0 = rtf(__expf(sacc[j][0] - mn0));
            float p1 = rtf(__expf(sacc[j][1] - mn0));
            float p2 = rtf(__expf(sacc[j][2] - mn1));
            float p3 = rtf(__expf(sacc[j][3] - mn1));
            sacc[j][0] = p0; sacc[j][1] = p1;
            sacc[j][2] = p2; sacc[j][3] = p3;
            rs0 += p0 + p1;  rs1 += p2 + p3;
        }
        rs0 += __shfl_xor_sync(0xffffffffu, rs0, 1);
        rs0 += __shfl_xor_sync(0xffffffffu, rs0, 2);
        rs1 += __shfl_xor_sync(0xffffffffu, rs1, 1);
        rs1 += __shfl_xor_sync(0xffffffffu, rs1, 2);
        l0 = l0*al0 + rs0;  l1 = l1*al1 + rs1;
        m0 = mn0;           m1 = mn1;
#pragma unroll
        for (int j = 0; j < 8; j++) {
            oacc[j][0] *= al0; oacc[j][1] *= al0;
            oacc[j][2] *= al1; oacc[j][3] *= al1;
        }

        // ---- P -> warp-private smem strip (already tf32-rounded) ---------------
#pragma unroll
        for (int j = 0; j < 8; j++) {
            float2 a; a.x = sacc[j][0]; a.y = sacc[j][1];
            float2 b; b.x = sacc[j][2]; b.y = sacc[j][3];
            *(float2*)&Ps[(wm + gid    )*APP + j*8 + 2*tig] = a;
            *(float2*)&Ps[(wm + gid + 8)*APP + j*8 + 2*tig] = b;
        }
        __syncwarp();

        // ---- O += P @ V (raw bit loads) ----------------------------------------
#pragma unroll
        for (int kc = 0; kc < 8; kc++) {
            uint32_t af[4];
            const float* pp = Ps + (wm + gid)*APP + kc*8 + tig;
            af[0] = __float_as_uint(pp[0]);
            af[1] = __float_as_uint(pp[8*APP]);
            af[2] = __float_as_uint(pp[4]);
            af[3] = __float_as_uint(pp[8*APP + 4]);
#pragma unroll
            for (int j = 0; j < 8; j++) {
                uint32_t bf[2];
                const float* vp = Vs + (kc*8 + tig)*AVP + j*8 + gid;
                bf[0] = __float_as_uint(vp[0]);
                bf[1] = __float_as_uint(vp[4*AVP]);
                mma_tf32(oacc[j], af, bf);
            }
        }
        __syncthreads();
    }

    // ---- epilogue (tf32-rounded: feeds the out-proj GEMM) ------------------------
    int b = bh >> 4, h = bh & 15;
    int r0 = qt*AQT + wm + gid;
    float inv0 = 1.f / l0, inv1 = 1.f / l1;
#pragma unroll
    for (int j = 0; j < 8; j++) {
        int col = h*HD_ + j*8 + 2*tig;
        float2 a; a.x = rtf(oacc[j][0]*inv0); a.y = rtf(oacc[j][1]*inv0);
        float2 c; c.x = rtf(oacc[j][2]*inv1); c.y = rtf(oacc[j][3]*inv1);
        *(float2*)&out[((size_t)(b*S_ + r0    ))*D_ + col] = a;
        *(float2*)&out[((size_t)(b*S_ + r0 + 8))*D_ + col] = c;
    }
}

// ================= TF32 tensor-core GEMM (pre-rounded operands) ===================
#define GBM 128
#define GBN 128
#define GBK 16
#define AP  20
#define BP  136

__device__ __forceinline__ float gelu_t(float x)
{
    float x3 = x*x*x;
    return 0.5f*x*(1.f + tanhf(0.7978845608028654f*(x + 0.044715f*x3)));
}

// MODE 0: C = acc
// MODE 1: C = res + gate*acc
// MODE 2: C = tf32(gelu(acc + bias))
// MODE 3: C = res + gate*(acc + bias)
template <int MODE>
__global__ __launch_bounds__(256)
void mma_gemm(const float* __restrict__ A, const float* __restrict__ Bm,
              float* __restrict__ C, int N, int K,
              const float* __restrict__ res, const float* __restrict__ bias,
              const float* __restrict__ mod, int gate_off)
{
    __shared__ float As[2][GBM*AP];
    __shared__ float Bs[2][GBK*BP];

    int tid  = threadIdx.x;
    int warp = tid >> 5, lane = tid & 31;
    int wm   = (warp >> 2) * 64;
    int wn   = (warp & 3)  * 32;
    int gid  = lane >> 2;
    int tig  = lane & 3;

    const float* Ap = A  + (size_t)blockIdx.y * GBM * K;
    const float* Bp = Bm + blockIdx.x * GBN;

    int ar = tid >> 1;
    int ac = (tid & 1) * 8;
    int bk = tid >> 4;
    int bn = (tid & 15) * 8;

    float acc[4][4][4];
#pragma unroll
    for (int i = 0; i < 4; i++)
#pragma unroll
        for (int j = 0; j < 4; j++)
#pragma unroll
            for (int q = 0; q < 4; q++) acc[i][j][q] = 0.f;

    {
        const float* ag = Ap + (size_t)ar*K + ac;
        cp_async16(&As[0][ar*AP + ac],     ag);
        cp_async16(&As[0][ar*AP + ac + 4], ag + 4);
        const float* bg = Bp + (size_t)bk*N + bn;
        cp_async16(&Bs[0][bk*BP + bn],     bg);
        cp_async16(&Bs[0][bk*BP + bn + 4], bg + 4);
    }
    CP_COMMIT();

    int buf = 0;
    for (int k0 = 0; k0 < K; k0 += GBK) {
        if (k0 + GBK < K) {
            const float* ag = Ap + (size_t)ar*K + (k0 + GBK) + ac;
            cp_async16(&As[buf^1][ar*AP + ac],     ag);
            cp_async16(&As[buf^1][ar*AP + ac + 4], ag + 4);
            const float* bg = Bp + (size_t)(k0 + GBK + bk)*N + bn;
            cp_async16(&Bs[buf^1][bk*BP + bn],     bg);
            cp_async16(&Bs[buf^1][bk*BP + bn + 4], bg + 4);
        }
        CP_COMMIT();
        CP_WAIT1();
        __syncthreads();

        const float* as = As[buf];
        const float* bs = Bs[buf];
#pragma unroll
        for (int kc = 0; kc < GBK; kc += 8) {
            uint32_t af[4][4], bf[4][2];
#pragma unroll
            for (int i = 0; i < 4; i++) {
                int r0 = wm + i*16 + gid;
                af[i][0] = __float_as_uint(as[ r0     *AP + kc + tig]);
                af[i][1] = __float_as_uint(as[(r0 + 8)*AP + kc + tig]);
                af[i][2] = __float_as_uint(as[ r0     *AP + kc + tig + 4]);
                af[i][3] = __float_as_uint(as[(r0 + 8)*AP + kc + tig + 4]);
            }
#pragma unroll
            for (int j = 0; j < 4; j++) {
                int n0 = wn + j*8 + gid;
                bf[j][0] = __float_as_uint(bs[(kc + tig    )*BP + n0]);
                bf[j][1] = __float_as_uint(bs[(kc + tig + 4)*BP + n0]);
            }
#pragma unroll
            for (int i = 0; i < 4; i++)
#pragma unroll
                for (int j = 0; j < 4; j++)
                    mma_tf32(acc[i][j], af[i], bf[j]);
        }
        __syncthreads();
        buf ^= 1;
    }

    int row_base = blockIdx.y*GBM + wm;
    int col_base = blockIdx.x*GBN + wn;
    int bb = (blockIdx.y * GBM) >> 11;
    const float* modb = (MODE == 1 || MODE == 3)
                      ? (mod + bb*SIXD_ + gate_off) : nullptr;
#pragma unroll
    for (int i = 0; i < 4; i++) {
        int r0 = row_base + i*16 + gid;
#pragma unroll
        for (int j = 0; j < 4; j++) {
            int c0 = col_base + j*8 + tig*2;
#pragma unroll
            for (int h = 0; h < 2; h++) {
                int row = r0 + h*8;
                float v0 = acc[i][j][h*2 + 0];
                float v1 = acc[i][j][h*2 + 1];
                if (MODE == 1) {
                    float2 rv = *(const float2*)(res + (size_t)row*N + c0);
                    v0 = rv.x + modb[c0    ]*v0;
                    v1 = rv.y + modb[c0 + 1]*v1;
                } else if (MODE == 2) {
                    v0 = rtf(gelu_t(v0 + bias[c0]));
                    v1 = rtf(gelu_t(v1 + bias[c0 + 1]));
                } else if (MODE == 3) {
                    float2 rv = *(const float2*)(res + (size_t)row*N + c0);
                    v0 = rv.x + modb[c0    ]*(v0 + bias[c0]);
                    v1 = rv.y + modb[c0 + 1]*(v1 + bias[c0 + 1]);
                }
                float2 st; st.x = v0; st.y = v1;
                *(float2*)(C + (size_t)row*N + c0) = st;
            }
        }
    }
}

// ---------------- launch ---------------------------------------------------------
extern "C" void kernel_launch(void* const* d_in, const int* in_sizes, int n_in,
                              void* d_out, int out_size)
{
    const float* x      = (const float*)d_in[0];
    const float* cosp   = (const float*)d_in[1];
    const float* sinp   = (const float*)d_in[2];
    const float* c      = (const float*)d_in[3];
    const float* n1w    = (const float*)d_in[4];
    const float* Wqkv   = (const float*)d_in[5];
    const float* Wout   = (const float*)d_in[6];
    const float* qw     = (const float*)d_in[7];
    const float* kw     = (const float*)d_in[8];
    const float* n2w    = (const float*)d_in[9];
    const float* W1     = (const float*)d_in[10];
    const float* b1     = (const float*)d_in[11];
    const float* W2     = (const float*)d_in[12];
    const float* b2     = (const float*)d_in[13];
    const float* adaW   = (const float*)d_in[14];
    const float* adab   = (const float*)d_in[15];
    float* out = (float*)d_out;

    float *p_mod, *p_xn, *p_qkv, *p_q, *p_k, *p_v, *p_attn, *p_x2, *p_h;
    float *p_wqkv, *p_wout, *p_w1, *p_w2;
    cudaGetSymbolAddress((void**)&p_mod,  g_mod);
    cudaGetSymbolAddress((void**)&p_xn,   g_xn);
    cudaGetSymbolAddress((void**)&p_qkv,  g_qkv);
    cudaGetSymbolAddress((void**)&p_q,    g_q);
    cudaGetSymbolAddress((void**)&p_k,    g_k);
    cudaGetSymbolAddress((void**)&p_v,    g_v);
    cudaGetSymbolAddress((void**)&p_attn, g_attn);
    cudaGetSymbolAddress((void**)&p_x2,   g_x2);
    cudaGetSymbolAddress((void**)&p_h,    g_h);
    cudaGetSymbolAddress((void**)&p_wqkv, g_wqkv);
    cudaGetSymbolAddress((void**)&p_wout, g_wout);
    cudaGetSymbolAddress((void**)&p_w1,   g_w1);
    cudaGetSymbolAddress((void**)&p_w2,   g_w2);

    cudaFuncSetAttribute(attn_mma_kernel,
                         cudaFuncAttributeMaxDynamicSharedMemorySize, ATTN_SMEM);

    // 0. pre-round weights to tf32 (removes all cvt from GEMM mainloops)
    round_tf32_kernel<<<(D_*3*D_)/1024, 256>>>(Wqkv, p_wqkv);
    round_tf32_kernel<<<(D_*D_)/1024,   256>>>(Wout, p_wout);
    round_tf32_kernel<<<(D_*DFF_)/1024, 256>>>(W1,   p_w1);
    round_tf32_kernel<<<(DFF_*D_)/1024, 256>>>(W2,   p_w2);

    // 1. adaLN modulation
    mod_kernel<<<dim3(SIXD_/256, B_), 256>>>(c, adaW, adab, p_mod);
    // 2. LN1 + modulate (tf32-rounded out)
    ln_mod_kernel<<<T_, 256>>>(x, n1w, p_mod, p_xn, 0, D_);
    // 3. QKV projection
    mma_gemm<0><<<dim3(3*D_/GBN, T_/GBM), 256>>>(p_xn, p_wqkv, p_qkv,
                                                 3*D_, D_, nullptr, nullptr,
                                                 nullptr, 0);
    // 4. qk-RMSNorm + RoPE + relayout (tf32-rounded out)
    qk_rope_kernel<<<T_, 512>>>(p_qkv, cosp, sinp, qw, kw, p_q, p_k, p_v);
    // 5. attention
    attn_mma_kernel<<<dim3(S_/AQT, B_*H_), 256, ATTN_SMEM>>>(p_q, p_k, p_v,
                                                             p_attn);
    // 6. out-proj + gated residual (gate = g_msa at 2D)
    mma_gemm<1><<<dim3(D_/GBN, T_/GBM), 256>>>(p_attn, p_wout, p_x2,
                                               D_, D_, x, nullptr,
                                               p_mod, 2*D_);
    // 7. LN2 + modulate (shift 3D, scale 4D; tf32-rounded out)
    ln_mod_kernel<<<T_, 256>>>(p_x2, n2w, p_mod, p_xn, 3*D_, 4*D_);
    // 8. MLP up + gelu (tf32-rounded out)
    mma_gemm<2><<<dim3(DFF_/GBN, T_/GBM), 256>>>(p_xn, p_w1, p_h,
                                                 DFF_, D_, nullptr, b1,
                                                 nullptr, 0);
    // 9. MLP down + gated residual (gate = g_mlp at 5D)
    mma_gemm<3><<<dim3(D_/GBN, T_/GBM), 256>>>(p_h, p_w2, out,
                                               D_, DFF_, p_x2, b2,
                                               p_mod, 5*D_);
}

// round 9
// speedup vs baseline: 1.7540x; 1.7540x over previous
#include <cuda_runtime.h>
#include <cuda_fp16.h>
#include <math.h>
#include <stdint.h>

#define D_    1024
#define H_    16
#define HD_   64
#define S_    2048
#define B_    4
#define T_    (B_*S_)      // 8192 tokens
#define DFF_  4096
#define SIXD_ 6144

// ---------------- scratch (static device globals; no allocation) ----------------
__device__ float  g_mod [B_*SIXD_];
__device__ __half g_xn  [(size_t)T_*D_];
__device__ __half g_qkv [(size_t)T_*3*D_];
__device__ __half g_q   [(size_t)B_*H_*S_*HD_];
__device__ __half g_k   [(size_t)B_*H_*S_*HD_];
__device__ __half g_v   [(size_t)B_*H_*S_*HD_];   // pair-interleaved: [bh][s/2][hd][2]
__device__ __half g_attn[(size_t)T_*D_];
__device__ float  g_x2  [(size_t)T_*D_];
__device__ __half g_h   [(size_t)T_*DFF_];
// half, k-pair-interleaved weights: wh2[k2][n] = (W[2k2][n], W[2k2+1][n])
__device__ __half g_wqkv[(size_t)D_*3*D_];
__device__ __half g_wout[(size_t)D_*D_];
__device__ __half g_w1  [(size_t)D_*DFF_];
__device__ __half g_w2  [(size_t)DFF_*D_];

// ---------------- async copy / mma helpers ---------------------------------------
__device__ __forceinline__ void cp_async16(void* smem, const void* gmem)
{
    uint32_t sa = (uint32_t)__cvta_generic_to_shared(smem);
    asm volatile("cp.async.cg.shared.global [%0], [%1], 16;\n"
                 :: "r"(sa), "l"(gmem));
}
#define CP_COMMIT()  asm volatile("cp.async.commit_group;\n" ::: "memory")
#define CP_WAIT1()   asm volatile("cp.async.wait_group 1;\n" ::: "memory")
#define CP_WAITALL() asm volatile("cp.async.wait_all;\n" ::: "memory")

// fp16 m16n8k16, fp32 accumulate
__device__ __forceinline__ void mma_f16(float* c, const uint32_t* a,
                                        const uint32_t* b)
{
    asm volatile("mma.sync.aligned.m16n8k16.row.col.f32.f16.f16.f32 "
                 "{%0,%1,%2,%3}, {%4,%5,%6,%7}, {%8,%9}, {%0,%1,%2,%3};\n"
                 : "+f"(c[0]), "+f"(c[1]), "+f"(c[2]), "+f"(c[3])
                 : "r"(a[0]), "r"(a[1]), "r"(a[2]), "r"(a[3]),
                   "r"(b[0]), "r"(b[1]));
}

__device__ __forceinline__ uint32_t pack2(float lo, float hi)
{
    __half2 h = __floats2half2_rn(lo, hi);
    return *(uint32_t*)&h;
}

// ---------------- weight convert + k-pair interleave ------------------------------
// in:  W [K][N] fp32 ; out: wh2 [K/2][N] half2-as-2half (lo = even k)
__global__ void wconv_kernel(const float* __restrict__ in,
                             __half* __restrict__ out, int N)
{
    int idx = blockIdx.x * 256 + threadIdx.x;     // over (K/2)*(N/4)
    int k2 = idx / (N >> 2);
    int nc = (idx - k2*(N >> 2)) * 4;
    float4 e = *(const float4*)(in + (size_t)(2*k2    )*N + nc);
    float4 o = *(const float4*)(in + (size_t)(2*k2 + 1)*N + nc);
    uint4 r;
    r.x = pack2(e.x, o.x);  r.y = pack2(e.y, o.y);
    r.z = pack2(e.z, o.z);  r.w = pack2(e.w, o.w);
    *(uint4*)(out + ((size_t)k2*N + nc)*2) = r;
}

// ---------------- adaLN modulation ------------------------------------------------
__global__ void mod_kernel(const float* __restrict__ c,
                           const float* __restrict__ adaW,
                           const float* __restrict__ adab,
                           float* __restrict__ mod)
{
    int b = blockIdx.y;
    int j = blockIdx.x * 256 + threadIdx.x;
    __shared__ float cs[D_];
    for (int i = threadIdx.x; i < D_; i += 256) cs[i] = c[b*D_ + i];
    __syncthreads();
    float acc = adab[j];
#pragma unroll 4
    for (int k = 0; k < D_; k++)
        acc = fmaf(cs[k], adaW[(size_t)k*SIXD_ + j], acc);
    mod[b*SIXD_ + j] = acc;
}

// ---------------- LayerNorm + modulate (half output) ------------------------------
__global__ void ln_mod_kernel(const float* __restrict__ x,
                              const float* __restrict__ w,
                              const float* __restrict__ mod,
                              __half* __restrict__ out,
                              int sh_off, int sc_off)
{
    int t = blockIdx.x;
    int b = t / S_;
    int tid = threadIdx.x;
    float4 v = ((const float4*)(x + (size_t)t*D_))[tid];
    float s  = v.x + v.y + v.z + v.w;
    float sq = v.x*v.x + v.y*v.y + v.z*v.z + v.w*v.w;
#pragma unroll
    for (int o = 16; o > 0; o >>= 1) {
        s  += __shfl_xor_sync(0xffffffffu, s,  o);
        sq += __shfl_xor_sync(0xffffffffu, sq, o);
    }
    __shared__ float ss[8], ssq[8];
    int warp = tid >> 5, lane = tid & 31;
    if (lane == 0) { ss[warp] = s; ssq[warp] = sq; }
    __syncthreads();
    if (warp == 0) {
        s  = (lane < 8) ? ss[lane]  : 0.f;
        sq = (lane < 8) ? ssq[lane] : 0.f;
#pragma unroll
        for (int o = 4; o > 0; o >>= 1) {
            s  += __shfl_xor_sync(0xffffffffu, s,  o);
            sq += __shfl_xor_sync(0xffffffffu, sq, o);
        }
        if (lane == 0) { ss[0] = s; ssq[0] = sq; }
    }
    __syncthreads();
    s = ss[0]; sq = ssq[0];
    float mu   = s  * (1.f/D_);
    float var  = sq * (1.f/D_) - mu*mu;
    float rsig = rsqrtf(var + 1e-5f);

    const float* modb = mod + b*SIXD_;
    float4 wv  = ((const float4*)w)[tid];
    float4 shv = ((const float4*)(modb + sh_off))[tid];
    float4 scv = ((const float4*)(modb + sc_off))[tid];
    uint2 r;
    r.x = pack2(fmaf((v.x-mu)*rsig*wv.x, (1.f+scv.x), shv.x),
                fmaf((v.y-mu)*rsig*wv.y, (1.f+scv.y), shv.y));
    r.y = pack2(fmaf((v.z-mu)*rsig*wv.z, (1.f+scv.z), shv.z),
                fmaf((v.w-mu)*rsig*wv.w, (1.f+scv.w), shv.w));
    *(uint2*)(out + (size_t)t*D_ + tid*4) = r;
}

// ---------------- RMSNorm(q,k) + RoPE + relayout (half out) -----------------------
__global__ void qk_rope_kernel(const __half* __restrict__ qkv,
                               const float* __restrict__ cosp,
                               const float* __restrict__ sinp,
                               const float* __restrict__ qw,
                               const float* __restrict__ kw,
                               __half* __restrict__ Q,
                               __half* __restrict__ K,
                               __half* __restrict__ V)
{
    int t = blockIdx.x;
    int s = t % S_;
    int b = t / S_;
    int h    = threadIdx.x >> 5;
    int lane = threadIdx.x & 31;
    const __half* base = qkv + (size_t)t*3*D_ + h*HD_;
    float q0 = __half2float(base[lane]);
    float q1 = __half2float(base[lane+32]);
    float k0 = __half2float(base[D_+lane]);
    float k1 = __half2float(base[D_+lane+32]);
    float v0 = __half2float(base[2*D_+lane]);
    float v1 = __half2float(base[2*D_+lane+32]);

    float qs = q0*q0 + q1*q1;
    float ks = k0*k0 + k1*k1;
#pragma unroll
    for (int o = 16; o > 0; o >>= 1) {
        qs += __shfl_xor_sync(0xffffffffu, qs, o);
        ks += __shfl_xor_sync(0xffffffffu, ks, o);
    }
    float qr = rsqrtf(qs*(1.f/HD_) + 1e-6f);
    float kr = rsqrtf(ks*(1.f/HD_) + 1e-6f);
    q0 *= qr*qw[lane];  q1 *= qr*qw[lane+32];
    k0 *= kr*kw[lane];  k1 *= kr*kw[lane+32];

    float c0 = cosp[s*HD_+lane], c1 = cosp[s*HD_+lane+32];
    float n0 = sinp[s*HD_+lane], n1 = sinp[s*HD_+lane+32];
    float qo0 = (q0*c0 - q1*n0) * 0.125f;
    float qo1 = (q1*c1 + q0*n1) * 0.125f;
    float ko0 =  k0*c0 - k1*n0;
    float ko1 =  k1*c1 + k0*n1;

    int bh = b*H_ + h;
    size_t o = ((size_t)bh*S_ + s)*HD_;
    Q[o+lane]    = __float2half_rn(qo0);
    Q[o+lane+32] = __float2half_rn(qo1);
    K[o+lane]    = __float2half_rn(ko0);
    K[o+lane+32] = __float2half_rn(ko1);
    // V pair-interleaved along s: V[((bh*S/2 + s/2)*HD + hd)*2 + (s&1)]
    size_t vb = ((size_t)bh*(S_/2) + (s >> 1))*HD_;
    V[(vb + lane   )*2 + (s & 1)] = __float2half_rn(v0);
    V[(vb + lane+32)*2 + (s & 1)] = __float2half_rn(v1);
}

// ================= fp16 tensor-core flash attention ===============================
// Word (=half2) pitches: A-class pitch%8==4 (Q/K/P = 36), B-class pitch%32==8 (V=72)
#define AQT 128
#define AKT 64
#define QP2 36
#define KP2 36
#define VP2 72
#define PP2 36
#define QS_W (AQT*QP2)          // 4608
#define KS_W (AKT*KP2)          // 2304
#define VS_W ((AKT/2)*VP2)      // 2304
#define PS_W (AQT*PP2)          // 4608
#define ATTN_SMEM ((QS_W + KS_W + VS_W + PS_W) * 4)   // 55296 B

__global__ __launch_bounds__(256, 2)
void attn_mma_kernel(const __half* __restrict__ Q,
                     const __half* __restrict__ K,
                     const __half* __restrict__ V,
                     __half* __restrict__ out)
{
    extern __shared__ uint32_t smu[];
    uint32_t* Qs = smu;
    uint32_t* Ks = Qs + QS_W;
    uint32_t* Vs = Ks + KS_W;
    uint32_t* Ps = Vs + VS_W;

    int bh  = blockIdx.y;
    int qt  = blockIdx.x;
    int tid = threadIdx.x;
    int warp = tid >> 5, lane = tid & 31;
    int gid = lane >> 2, tig = lane & 3;
    int wm = warp * 16;

    // Q tile: 128 rows x 32 half2 (8 x 16B chunks/row)
    const __half* Qb = Q + ((size_t)bh*S_ + qt*AQT)*HD_;
    {
        int qr = tid >> 1, qc2 = (tid & 1) * 16;
#pragma unroll
        for (int c = 0; c < 4; c++)
            cp_async16(&Qs[qr*QP2 + qc2 + c*4], Qb + qr*HD_ + (qc2 + c*4)*2);
    }
    CP_COMMIT();

    float m0 = -1e30f, m1 = -1e30f, l0 = 0.f, l1 = 0.f;
    float oacc[8][4];
#pragma unroll
    for (int j = 0; j < 8; j++)
#pragma unroll
        for (int q = 0; q < 4; q++) oacc[j][q] = 0.f;

    const __half* Kb0 = K + (size_t)bh*S_*HD_;
    const __half* Vb0 = V + (size_t)bh*(S_/2)*HD_*2;   // interleaved half2 rows

    for (int kt = 0; kt < S_/AKT; kt++) {
        // K tile: 64 rows x 32 half2
        {
            int kr = tid >> 2, kc2 = (tid & 3) * 8;
            const __half* Kb = Kb0 + (size_t)(kt*AKT + kr)*HD_;
            cp_async16(&Ks[kr*KP2 + kc2    ], Kb + kc2*2);
            cp_async16(&Ks[kr*KP2 + kc2 + 4], Kb + kc2*2 + 8);
        }
        // V tile: 32 k2-rows x 64 half2
        {
            int vr = tid >> 3, vc2 = (tid & 7) * 8;
            const __half* Vb = Vb0 + ((size_t)(kt*(AKT/2) + vr)*HD_ + vc2)*2;
            cp_async16(&Vs[vr*VP2 + vc2    ], Vb);
            cp_async16(&Vs[vr*VP2 + vc2 + 4], Vb + 8);
        }
        CP_COMMIT();
        CP_WAITALL();
        __syncthreads();

        // ---- S = Q @ K^T -------------------------------------------------------
        float sacc[8][4];
#pragma unroll
        for (int j = 0; j < 8; j++)
#pragma unroll
            for (int q = 0; q < 4; q++) sacc[j][q] = 0.f;

#pragma unroll
        for (int kc = 0; kc < 4; kc++) {           // kc2 = kc*8
            uint32_t af[4];
            const uint32_t* qp = Qs + (wm + gid)*QP2 + kc*8 + tig;
            af[0] = qp[0];
            af[1] = qp[8*QP2];
            af[2] = qp[4];
            af[3] = qp[8*QP2 + 4];
#pragma unroll
            for (int j = 0; j < 8; j++) {
                uint32_t bf[2];
                const uint32_t* kp = Ks + (j*8 + gid)*KP2 + kc*8 + tig;
                bf[0] = kp[0];
                bf[1] = kp[4];
                mma_f16(sacc[j], af, bf);
            }
        }

        // ---- online softmax; round P to fp16 (consistent with PV sum) ----------
        float mx0 = -1e30f, mx1 = -1e30f;
#pragma unroll
        for (int j = 0; j < 8; j++) {
            mx0 = fmaxf(mx0, fmaxf(sacc[j][0], sacc[j][1]));
            mx1 = fmaxf(mx1, fmaxf(sacc[j][2], sacc[j][3]));
        }
        mx0 = fmaxf(mx0, __shfl_xor_sync(0xffffffffu, mx0, 1));
        mx0 = fmaxf(mx0, __shfl_xor_sync(0xffffffffu, mx0, 2));
        mx1 = fmaxf(mx1, __shfl_xor_sync(0xffffffffu, mx1, 1));
        mx1 = fmaxf(mx1, __shfl_xor_sync(0xffffffffu, mx1, 2));
        float mn0 = fmaxf(m0, mx0), mn1 = fmaxf(m1, mx1);
        float al0 = __expf(m0 - mn0), al1 = __expf(m1 - mn1);
        float rs0 = 0.f, rs1 = 0.f;
#pragma unroll
        for (int j = 0; j < 8; j++) {
            __half2 pa = __floats2half2_rn(__expf(sacc[j][0] - mn0),
                                           __expf(sacc[j][1] - mn0));
            __half2 pb = __floats2half2_rn(__expf(sacc[j][2] - mn1),
                                           __expf(sacc[j][3] - mn1));
            float2 fa = __half22float2(pa);
            float2 fb = __half22float2(pb);
            rs0 += fa.x + fa.y;  rs1 += fb.x + fb.y;
            Ps[(wm + gid    )*PP2 + j*4 + tig] = *(uint32_t*)&pa;
            Ps[(wm + gid + 8)*PP2 + j*4 + tig] = *(uint32_t*)&pb;
        }
        rs0 += __shfl_xor_sync(0xffffffffu, rs0, 1);
        rs0 += __shfl_xor_sync(0xffffffffu, rs0, 2);
        rs1 += __shfl_xor_sync(0xffffffffu, rs1, 1);
        rs1 += __shfl_xor_sync(0xffffffffu, rs1, 2);
        l0 = l0*al0 + rs0;  l1 = l1*al1 + rs1;
        m0 = mn0;           m1 = mn1;
#pragma unroll
        for (int j = 0; j < 8; j++) {
            oacc[j][0] *= al0; oacc[j][1] *= al0;
            oacc[j][2] *= al1; oacc[j][3] *= al1;
        }
        __syncwarp();

        // ---- O += P @ V --------------------------------------------------------
#pragma unroll
        for (int kc = 0; kc < 4; kc++) {
            uint32_t af[4];
            const uint32_t* pp = Ps + (wm + gid)*PP2 + kc*8 + tig;
            af[0] = pp[0];
            af[1] = pp[8*PP2];
            af[2] = pp[4];
            af[3] = pp[8*PP2 + 4];
#pragma unroll
            for (int j = 0; j < 8; j++) {
                uint32_t bf[2];
                const uint32_t* vp = Vs + (kc*8 + tig)*VP2 + j*8 + gid;
                bf[0] = vp[0];
                bf[1] = vp[4*VP2];
                mma_f16(oacc[j], af, bf);
            }
        }
        __syncthreads();
    }

    // ---- epilogue -> g_attn (half) ---------------------------------------------
    int b = bh >> 4, h = bh & 15;
    int r0 = qt*AQT + wm + gid;
    float inv0 = 1.f / l0, inv1 = 1.f / l1;
#pragma unroll
    for (int j = 0; j < 8; j++) {
        int col = h*HD_ + j*8 + 2*tig;
        *(__half2*)&out[((size_t)(b*S_ + r0    ))*D_ + col] =
            __floats2half2_rn(oacc[j][0]*inv0, oacc[j][1]*inv0);
        *(__half2*)&out[((size_t)(b*S_ + r0 + 8))*D_ + col] =
            __floats2half2_rn(oacc[j][2]*inv1, oacc[j][3]*inv1);
    }
}

// ================= fp16 tensor-core GEMM with fused epilogues =====================
// Block 128x128, GBK=32 (16 half2), 8 warps (2M x 4N), warp tile 64x32.
// A smem [128][AP2=20] half2-words; B smem [16][BP2=136] half2-words.
#define GBM 128
#define GBN 128
#define GBK 32
#define AP2 20
#define BP2 136

__device__ __forceinline__ float gelu_t(float x)
{
    float x3 = x*x*x;
    return 0.5f*x*(1.f + tanhf(0.7978845608028654f*(x + 0.044715f*x3)));
}

// MODE 0: C(half) = acc                       (QKV)
// MODE 1: C(float) = res + gate*acc           (out-proj + residual)
// MODE 2: C(half) = gelu(acc + bias)          (MLP up)
// MODE 3: C(float) = res + gate*(acc + bias)  (MLP down + residual)
template <int MODE>
__global__ __launch_bounds__(256)
void mma_gemm(const __half* __restrict__ A, const __half* __restrict__ Bm,
              void* __restrict__ Cv, int N, int K,
              const float* __restrict__ res, const float* __restrict__ bias,
              const float* __restrict__ mod, int gate_off)
{
    __shared__ uint32_t As[2][GBM*AP2];   // 20480 B
    __shared__ uint32_t Bs[2][16*BP2];    // 17408 B

    int tid  = threadIdx.x;
    int warp = tid >> 5, lane = tid & 31;
    int wm   = (warp >> 2) * 64;
    int wn   = (warp & 3)  * 32;
    int gid  = lane >> 2;
    int tig  = lane & 3;

    const __half* Ap = A  + (size_t)blockIdx.y * GBM * K;
    const __half* Bp = Bm + (size_t)blockIdx.x * GBN * 2;   // half2 col offset *2 halves

    // A: row ar, two 16B chunks at half2 offsets ac2, ac2+4
    int ar  = tid >> 1;
    int ac2 = (tid & 1) * 8;
    // B: k2-row bk2, two chunks at half2 offsets bn2, bn2+4 (within 128-wide tile)
    int bk2 = tid >> 4;
    int bn2 = (tid & 15) * 8;

    float acc[4][4][4];
#pragma unroll
    for (int i = 0; i < 4; i++)
#pragma unroll
        for (int j = 0; j < 4; j++)
#pragma unroll
            for (int q = 0; q < 4; q++) acc[i][j][q] = 0.f;

    {
        const __half* ag = Ap + (size_t)ar*K + ac2*2;
        cp_async16(&As[0][ar*AP2 + ac2],     ag);
        cp_async16(&As[0][ar*AP2 + ac2 + 4], ag + 8);
        const __half* bg = Bp + ((size_t)bk2*N + bn2)*2;
        cp_async16(&Bs[0][bk2*BP2 + bn2],     bg);
        cp_async16(&Bs[0][bk2*BP2 + bn2 + 4], bg + 8);
    }
    CP_COMMIT();

    int buf = 0;
    for (int k0 = 0; k0 < K; k0 += GBK) {
        if (k0 + GBK < K) {
            const __half* ag = Ap + (size_t)ar*K + (k0 + GBK) + ac2*2;
            cp_async16(&As[buf^1][ar*AP2 + ac2],     ag);
            cp_async16(&As[buf^1][ar*AP2 + ac2 + 4], ag + 8);
            const __half* bg = Bp + ((size_t)((k0 + GBK)/2 + bk2)*N + bn2)*2;
            cp_async16(&Bs[buf^1][bk2*BP2 + bn2],     bg);
            cp_async16(&Bs[buf^1][bk2*BP2 + bn2 + 4], bg + 8);
        }
        CP_COMMIT();
        CP_WAIT1();
        __syncthreads();

        const uint32_t* as = As[buf];
        const uint32_t* bs = Bs[buf];
#pragma unroll
        for (int kc = 0; kc < 2; kc++) {            // kc2 = kc*8 (k=16 per step)
            uint32_t af[4][4], bf[4][2];
#pragma unroll
            for (int i = 0; i < 4; i++) {
                int r0 = wm + i*16 + gid;
                const uint32_t* ap = as + r0*AP2 + kc*8 + tig;
                af[i][0] = ap[0];
                af[i][1] = ap[8*AP2];
                af[i][2] = ap[4];
                af[i][3] = ap[8*AP2 + 4];
            }
#pragma unroll
            for (int j = 0; j < 4; j++) {
                int n0 = wn + j*8 + gid;
                bf[j][0] = bs[(kc*8 + tig    )*BP2 + n0];
                bf[j][1] = bs[(kc*8 + tig + 4)*BP2 + n0];
            }
#pragma unroll
            for (int i = 0; i < 4; i++)
#pragma unroll
                for (int j = 0; j < 4; j++)
                    mma_f16(acc[i][j], af[i], bf[j]);
        }
        __syncthreads();
        buf ^= 1;
    }

    int row_base = blockIdx.y*GBM + wm;
    int col_base = blockIdx.x*GBN + wn;
    int bb = (blockIdx.y * GBM) >> 11;
    const float* modb = (MODE == 1 || MODE == 3)
                      ? (mod + bb*SIXD_ + gate_off) : nullptr;
#pragma unroll
    for (int i = 0; i < 4; i++) {
        int r0 = row_base + i*16 + gid;
#pragma unroll
        for (int j = 0; j < 4; j++) {
            int c0 = col_base + j*8 + tig*2;
#pragma unroll
            for (int h = 0; h < 2; h++) {
                int row = r0 + h*8;
                float v0 = acc[i][j][h*2 + 0];
                float v1 = acc[i][j][h*2 + 1];
                if (MODE == 0) {
                    *(__half2*)((__half*)Cv + (size_t)row*N + c0) =
                        __floats2half2_rn(v0, v1);
                } else if (MODE == 1) {
                    float2 rv = *(const float2*)(res + (size_t)row*N + c0);
                    float2 st;
                    st.x = rv.x + modb[c0    ]*v0;
                    st.y = rv.y + modb[c0 + 1]*v1;
                    *(float2*)((float*)Cv + (size_t)row*N + c0) = st;
                } else if (MODE == 2) {
                    *(__half2*)((__half*)Cv + (size_t)row*N + c0) =
                        __floats2half2_rn(gelu_t(v0 + bias[c0]),
                                          gelu_t(v1 + bias[c0 + 1]));
                } else {
                    float2 rv = *(const float2*)(res + (size_t)row*N + c0);
                    float2 st;
                    st.x = rv.x + modb[c0    ]*(v0 + bias[c0]);
                    st.y = rv.y + modb[c0 + 1]*(v1 + bias[c0 + 1]);
                    *(float2*)((float*)Cv + (size_t)row*N + c0) = st;
                }
            }
        }
    }
}

// ---------------- launch ---------------------------------------------------------
extern "C" void kernel_launch(void* const* d_in, const int* in_sizes, int n_in,
                              void* d_out, int out_size)
{
    const float* x      = (const float*)d_in[0];
    const float* cosp   = (const float*)d_in[1];
    const float* sinp   = (const float*)d_in[2];
    const float* c      = (const float*)d_in[3];
    const float* n1w    = (const float*)d_in[4];
    const float* Wqkv   = (const float*)d_in[5];
    const float* Wout   = (const float*)d_in[6];
    const float* qw     = (const float*)d_in[7];
    const float* kw     = (const float*)d_in[8];
    const float* n2w    = (const float*)d_in[9];
    const float* W1     = (const float*)d_in[10];
    const float* b1     = (const float*)d_in[11];
    const float* W2     = (const float*)d_in[12];
    const float* b2     = (const float*)d_in[13];
    const float* adaW   = (const float*)d_in[14];
    const float* adab   = (const float*)d_in[15];
    float* out = (float*)d_out;

    float *p_mod, *p_x2;
    __half *p_xn, *p_qkv, *p_q, *p_k, *p_v, *p_attn, *p_h;
    __half *p_wqkv, *p_wout, *p_w1, *p_w2;
    cudaGetSymbolAddress((void**)&p_mod,  g_mod);
    cudaGetSymbolAddress((void**)&p_xn,   g_xn);
    cudaGetSymbolAddress((void**)&p_qkv,  g_qkv);
    cudaGetSymbolAddress((void**)&p_q,    g_q);
    cudaGetSymbolAddress((void**)&p_k,    g_k);
    cudaGetSymbolAddress((void**)&p_v,    g_v);
    cudaGetSymbolAddress((void**)&p_attn, g_attn);
    cudaGetSymbolAddress((void**)&p_x2,   g_x2);
    cudaGetSymbolAddress((void**)&p_h,    g_h);
    cudaGetSymbolAddress((void**)&p_wqkv, g_wqkv);
    cudaGetSymbolAddress((void**)&p_wout, g_wout);
    cudaGetSymbolAddress((void**)&p_w1,   g_w1);
    cudaGetSymbolAddress((void**)&p_w2,   g_w2);

    cudaFuncSetAttribute(attn_mma_kernel,
                         cudaFuncAttributeMaxDynamicSharedMemorySize, ATTN_SMEM);

    // 0. weight convert + k-pair interleave to half
    wconv_kernel<<<(D_/2)*(3*D_/4)/256, 256>>>(Wqkv, p_wqkv, 3*D_);
    wconv_kernel<<<(D_/2)*(D_/4)/256,   256>>>(Wout, p_wout, D_);
    wconv_kernel<<<(D_/2)*(DFF_/4)/256, 256>>>(W1,   p_w1,   DFF_);
    wconv_kernel<<<(DFF_/2)*(D_/4)/256, 256>>>(W2,   p_w2,   D_);

    // 1. adaLN modulation
    mod_kernel<<<dim3(SIXD_/256, B_), 256>>>(c, adaW, adab, p_mod);
    // 2. LN1 + modulate -> half
    ln_mod_kernel<<<T_, 256>>>(x, n1w, p_mod, p_xn, 0, D_);
    // 3. QKV projection (fp16 mma) -> half
    mma_gemm<0><<<dim3(3*D_/GBN, T_/GBM), 256>>>(p_xn, p_wqkv, p_qkv,
                                                 3*D_, D_, nullptr, nullptr,
                                                 nullptr, 0);
    // 4. qk-RMSNorm + RoPE + relayout -> half (V pair-interleaved)
    qk_rope_kernel<<<T_, 512>>>(p_qkv, cosp, sinp, qw, kw, p_q, p_k, p_v);
    // 5. attention (fp16 mma flash) -> half
    attn_mma_kernel<<<dim3(S_/AQT, B_*H_), 256, ATTN_SMEM>>>(p_q, p_k, p_v,
                                                             p_attn);
    // 6. out-proj + gated residual (gate g_msa @2D) -> float
    mma_gemm<1><<<dim3(D_/GBN, T_/GBM), 256>>>(p_attn, p_wout, p_x2,
                                               D_, D_, x, nullptr,
                                               p_mod, 2*D_);
    // 7. LN2 + modulate (shift 3D, scale 4D) -> half
    ln_mod_kernel<<<T_, 256>>>(p_x2, n2w, p_mod, p_xn, 3*D_, 4*D_);
    // 8. MLP up + gelu -> half
    mma_gemm<2><<<dim3(DFF_/GBN, T_/GBM), 256>>>(p_xn, p_w1, p_h,
                                                 DFF_, D_, nullptr, b1,
                                                 nullptr, 0);
    // 9. MLP down + gated residual (gate g_mlp @5D) -> float (d_out)
    mma_gemm<3><<<dim3(D_/GBN, T_/GBM), 256>>>(p_h, p_w2, out,
                                               D_, DFF_, p_x2, b2,
                                               p_mod, 5*D_);
}